// round 3
// baseline (speedup 1.0000x reference)
#include <cuda_runtime.h>
#include <cuda_bf16.h>
#include <math.h>

// EMA with SD, chunked parallel scan.
// Shapes: x (T=8192, D=128); h_a0, h_sd0, alpha (N=32, D=128).
// Output: out (T, 2N, D) fp32, then hN_a (N,D), then hN_sd (N,D) flattened.
//
// Decomposition: C=32 chunks of L=256 steps.
//   beta = 1 - alpha
//   h_a[i]   = beta*h_a[i-1] + alpha*x[i]            (linear in chunk-entry h_a0)
//   h_v[i]   = beta*h_v[i-1] + beta*alpha*d[i]^2,  d[i] = x[i] - h_a[i-1]
// Within a chunk: h_a[i] = g[i] + beta^{i+1}*h_a0, d[i] = u[i] - beta^i*h_a0
// => chunk-end h_v = W*h_v0 + A + B*h_a0 + C*h_a0^2  (W = beta^L)
//    chunk-end h_a = W*h_a0 + P                       (P = g[L-1])
// Pass1 computes (W,P,A,B,C) per (chunk, n, d). Combine walks the 32 chunk
// summaries per lane to get exact chunk-entry states. Pass2 replays the exact
// per-step recurrence per chunk and streams the 268MB output.

#define TT 8192
#define DD 128
#define NN 32
#define CC 32
#define LL 256          // TT / CC
#define LANES (NN * DD) // 4096

// Scratch (device globals; no allocation allowed in kernel_launch).
__device__ float g_W [CC * LANES];
__device__ float g_P [CC * LANES];
__device__ float g_A [CC * LANES];
__device__ float g_B [CC * LANES];
__device__ float g_C [CC * LANES];
__device__ float g_ha0[CC * LANES];
__device__ float g_hv0[CC * LANES];

__global__ __launch_bounds__(DD) void ema_pass1(
    const float* __restrict__ x,
    const float* __restrict__ alpha)
{
    const int c = blockIdx.x;
    const int n = blockIdx.y;
    const int d = threadIdx.x;
    const int idx = n * DD + d;

    const float a  = alpha[idx];
    const float b  = 1.0f - a;
    const float ba = b * a;
    const float m2ba = -2.0f * ba;

    const float* xp = x + (size_t)c * LL * DD + d;

    float g = 0.0f, w = 1.0f;
    float A = 0.0f, B = 0.0f, Cq = 0.0f;

#pragma unroll 4
    for (int i = 0; i < LL; ++i) {
        const float xv = xp[(size_t)i * DD];
        const float u  = xv - g;            // uses g[i-1]
        g = fmaf(b, g, a * xv);             // g[i]
        A  = fmaf(b, A,  ba   * (u * u));
        B  = fmaf(b, B,  m2ba * (u * w));   // uses w = beta^i
        Cq = fmaf(b, Cq, ba   * (w * w));
        w *= b;
    }

    const int s = c * LANES + idx;
    g_W[s] = w;   // beta^L
    g_P[s] = g;
    g_A[s] = A;
    g_B[s] = B;
    g_C[s] = Cq;
}

__global__ __launch_bounds__(DD) void ema_combine(
    const float* __restrict__ h_a0,
    const float* __restrict__ h_sd0,
    float* __restrict__ out,
    int write_tail)
{
    const int n = blockIdx.x;
    const int d = threadIdx.x;
    const int idx = n * DD + d;

    float ha = h_a0[idx];
    const float sd = h_sd0[idx];
    float hv = sd * sd;

#pragma unroll 4
    for (int c = 0; c < CC; ++c) {
        const int s = c * LANES + idx;
        g_ha0[s] = ha;
        g_hv0[s] = hv;
        const float W  = g_W[s];
        const float P  = g_P[s];
        const float A  = g_A[s];
        const float B  = g_B[s];
        const float Cq = g_C[s];
        const float hv_new = fmaf(W, hv, fmaf(Cq, ha * ha, fmaf(B, ha, A)));
        hv = fmaxf(hv_new, 0.0f);
        ha = fmaf(W, ha, P);
    }

    if (write_tail) {
        const size_t base = (size_t)TT * 2 * NN * DD;
        out[base + idx]         = ha;          // hN_a
        out[base + LANES + idx] = sqrtf(hv);   // hN_sd
    }
}

__global__ __launch_bounds__(DD) void ema_pass2(
    const float* __restrict__ x,
    const float* __restrict__ alpha,
    float* __restrict__ out)
{
    const int c = blockIdx.x;
    const int n = blockIdx.y;
    const int d = threadIdx.x;
    const int idx = n * DD + d;

    const float a  = alpha[idx];
    const float b  = 1.0f - a;
    const float ba = b * a;

    const int s = c * LANES + idx;
    float ha = g_ha0[s];
    float hv = g_hv0[s];

    const float* xp = x + (size_t)c * LL * DD + d;
    const size_t row = (size_t)2 * NN * DD;               // 8192 floats per t
    float* oa = out + (size_t)c * LL * row + (size_t)n * DD + d;
    float* ov = oa + (size_t)NN * DD;

#pragma unroll 4
    for (int i = 0; i < LL; ++i) {
        const float xv = xp[(size_t)i * DD];
        const float u  = xv - ha;
        ha = fmaf(b, ha, a * xv);            // 4-cycle self-chain
        hv = fmaf(b, hv, ba * (u * u));      // 4-cycle self-chain
        oa[(size_t)i * row] = ha;
        ov[(size_t)i * row] = sqrtf(hv);
    }
}

extern "C" void kernel_launch(void* const* d_in, const int* in_sizes, int n_in,
                              void* d_out, int out_size)
{
    const float* x     = (const float*)d_in[0];
    const float* h_a0  = (const float*)d_in[1];
    const float* h_sd0 = (const float*)d_in[2];
    const float* alpha = (const float*)d_in[3];
    float* out = (float*)d_out;

    const int main_elems = TT * 2 * NN * DD;          // 67,108,864
    const int write_tail = (out_size > main_elems) ? 1 : 0;

    dim3 grid1(CC, NN);
    ema_pass1<<<grid1, DD>>>(x, alpha);
    ema_combine<<<NN, DD>>>(h_a0, h_sd0, out, write_tail);
    dim3 grid2(CC, NN);
    ema_pass2<<<grid2, DD>>>(x, alpha, out);
}

// round 4
// speedup vs baseline: 1.8333x; 1.8333x over previous
#include <cuda_runtime.h>
#include <cuda_bf16.h>
#include <math.h>

// EMA with SD, chunked parallel scan (round 4).
// Shapes: x (T=8192, D=128); h_a0, h_sd0, alpha (N=32, D=128).
// Output: out (T, 2N, D) fp32, then hN_a (N,D), then hN_sd (N,D).
//
// Chunk decomposition (C=64 chunks of L=128 steps), with closed forms:
//   beta = 1 - alpha, W = beta^L
//   chunk-end h_a = W*h_a0 + P,                 P = g[L-1]
//   chunk-end h_v = W*h_v0 + A + B*h_a0 + C*h_a0^2
//     A = sum_i beta^{L-1-i} * beta*alpha * u_i^2          (loop)
//     B = -2*beta*alpha*beta^{L-1} * sum_i u_i             (weights cancel!)
//     C = W*(1-W)                                          (closed form)
// Pass1 computes (P, A, S=sum u) per (chunk,n,d). Combine walks 64 chunk
// summaries per lane. Pass2 replays exact per-step recurrence with streaming
// (evict-first) stores so x stays L2-resident.

#define TT 8192
#define DD 128
#define NN 32
#define CC 64
#define LL 128          // TT / CC
#define LANES (NN * DD) // 4096

__device__ float g_P  [CC * LANES];
__device__ float g_A  [CC * LANES];
__device__ float g_S  [CC * LANES];
__device__ float g_ha0[CC * LANES];
__device__ float g_hv0[CC * LANES];

__device__ __forceinline__ float sqrt_fast(float v) {
    float r;
    asm("sqrt.approx.f32 %0, %1;" : "=f"(r) : "f"(v));
    return r;
}

// ---------------------------------------------------------------- pass 1
__global__ __launch_bounds__(64) void ema_pass1(
    const float* __restrict__ x,
    const float* __restrict__ alpha)
{
    const int c  = blockIdx.x;
    const int n  = blockIdx.y;
    const int d2 = threadIdx.x;          // 0..63, handles d = 2*d2, 2*d2+1
    const int idx = n * DD + 2 * d2;

    const float2 al = *reinterpret_cast<const float2*>(alpha + idx);
    const float a0 = al.x, a1 = al.y;
    const float b0 = 1.0f - a0, b1 = 1.0f - a1;
    const float ba0 = b0 * a0, ba1 = b1 * a1;

    const float2* xp = reinterpret_cast<const float2*>(x + (size_t)c * LL * DD + 2 * d2);

    float gA = 0.0f, gB = 0.0f;          // g accumulators (lane0/lane1)
    float A0 = 0.0f, A1 = 0.0f;
    float S0 = 0.0f, S1 = 0.0f;

#pragma unroll 8
    for (int i = 0; i < LL; ++i) {
        const float2 xv = xp[(size_t)i * (DD / 2)];
        const float u0 = xv.x - gA;
        const float u1 = xv.y - gB;
        gA = fmaf(b0, gA, a0 * xv.x);
        gB = fmaf(b1, gB, a1 * xv.y);
        A0 = fmaf(b0, A0, ba0 * (u0 * u0));
        A1 = fmaf(b1, A1, ba1 * (u1 * u1));
        S0 += u0;
        S1 += u1;
    }

    const int s = c * LANES + idx;
    *reinterpret_cast<float2*>(g_P + s) = make_float2(gA, gB);
    *reinterpret_cast<float2*>(g_A + s) = make_float2(A0, A1);
    *reinterpret_cast<float2*>(g_S + s) = make_float2(S0, S1);
}

// ---------------------------------------------------------------- combine
__global__ __launch_bounds__(DD) void ema_combine(
    const float* __restrict__ h_a0,
    const float* __restrict__ h_sd0,
    const float* __restrict__ alpha,
    float* __restrict__ out,
    int write_tail)
{
    const int n = blockIdx.x;
    const int d = threadIdx.x;
    const int idx = n * DD + d;

    const float a = alpha[idx];
    const float b = 1.0f - a;
    // b^(L-1) and W = b^L by repeated squaring (L = 128)
    const float s1 = b;            // b^1
    const float s2 = s1 * s1;      // b^2
    const float s4 = s2 * s2;      // b^4
    const float s8 = s4 * s4;      // b^8
    const float s16 = s8 * s8;     // b^16
    const float s32 = s16 * s16;   // b^32
    const float s64 = s32 * s32;   // b^64
    const float b127 = s1 * s2 * s4 * s8 * s16 * s32 * s64;  // b^127
    const float W  = s64 * s64;                               // b^128
    const float Cq = W * (1.0f - W);
    const float coefB = -2.0f * b * a * b127;

    float ha = h_a0[idx];
    const float sd = h_sd0[idx];
    float hv = sd * sd;

#pragma unroll 4
    for (int c = 0; c < CC; ++c) {
        const int s = c * LANES + idx;
        g_ha0[s] = ha;
        g_hv0[s] = hv;
        const float P = g_P[s];
        const float A = g_A[s];
        const float B = coefB * g_S[s];
        const float hv_new = fmaf(W, hv, fmaf(Cq, ha * ha, fmaf(B, ha, A)));
        hv = fmaxf(hv_new, 0.0f);
        ha = fmaf(W, ha, P);
    }

    if (write_tail) {
        const size_t base = (size_t)TT * 2 * NN * DD;
        out[base + idx]         = ha;          // hN_a
        out[base + LANES + idx] = sqrtf(hv);   // hN_sd
    }
}

// ---------------------------------------------------------------- pass 2
__global__ __launch_bounds__(64) void ema_pass2(
    const float* __restrict__ x,
    const float* __restrict__ alpha,
    float* __restrict__ out)
{
    const int c  = blockIdx.x;
    const int n  = blockIdx.y;
    const int d2 = threadIdx.x;          // 0..63
    const int idx = n * DD + 2 * d2;

    const float2 al = *reinterpret_cast<const float2*>(alpha + idx);
    const float a0 = al.x, a1 = al.y;
    const float b0 = 1.0f - a0, b1 = 1.0f - a1;
    const float ba0 = b0 * a0, ba1 = b1 * a1;

    const int s = c * LANES + idx;
    float2 ha = *reinterpret_cast<const float2*>(g_ha0 + s);
    float2 hv = *reinterpret_cast<const float2*>(g_hv0 + s);
    float ha0 = ha.x, ha1 = ha.y;
    float hv0 = hv.x, hv1 = hv.y;

    const float2* xp = reinterpret_cast<const float2*>(x + (size_t)c * LL * DD + 2 * d2);
    const size_t row2 = (size_t)NN * DD;   // 4096 floats -> 2048 float2 per t-half
    float2* oa = reinterpret_cast<float2*>(out) + (size_t)c * LL * row2 / 2 * 2
               /* see below: compute directly */;
    // out row for time t is 2*N*D = 8192 floats = 4096 float2.
    float2* obase = reinterpret_cast<float2*>(out + (size_t)c * LL * 2 * NN * DD + n * DD + 2 * d2);
    (void)oa; (void)row2;

#pragma unroll 8
    for (int i = 0; i < LL; ++i) {
        const float2 xv = xp[(size_t)i * (DD / 2)];
        const float u0 = xv.x - ha0;
        const float u1 = xv.y - ha1;
        ha0 = fmaf(b0, ha0, a0 * xv.x);
        ha1 = fmaf(b1, ha1, a1 * xv.y);
        hv0 = fmaf(b0, hv0, ba0 * (u0 * u0));
        hv1 = fmaf(b1, hv1, ba1 * (u1 * u1));
        // avg at (t, n, :), sd at (t, N+n, :). Row stride = 2*N*D floats = 4096 float2.
        float2* op = obase + (size_t)i * (NN * DD);   // i * 4096 float2
        __stcs(op, make_float2(ha0, ha1));
        __stcs(op + (NN * DD / 2), make_float2(sqrt_fast(hv0), sqrt_fast(hv1)));
    }
}

extern "C" void kernel_launch(void* const* d_in, const int* in_sizes, int n_in,
                              void* d_out, int out_size)
{
    const float* x     = (const float*)d_in[0];
    const float* h_a0  = (const float*)d_in[1];
    const float* h_sd0 = (const float*)d_in[2];
    const float* alpha = (const float*)d_in[3];
    float* out = (float*)d_out;

    const int main_elems = TT * 2 * NN * DD;
    const int write_tail = (out_size > main_elems) ? 1 : 0;

    dim3 grid1(CC, NN);
    ema_pass1<<<grid1, 64>>>(x, alpha);
    ema_combine<<<NN, DD>>>(h_a0, h_sd0, alpha, out, write_tail);
    dim3 grid2(CC, NN);
    ema_pass2<<<grid2, 64>>>(x, alpha, out);
}